// round 17
// baseline (speedup 1.0000x reference)
#include <cuda_runtime.h>

// Problem constants: T=1024, B=64, I=512, H=512, 3H=1536
#define NCTA 128
#define NTEAMS 8        // 8 teams x 16 CTAs; team tau owns b in {tau, tau+8, ..., tau+56}
#define NTHR 768        // 24 warps: 6 rowgroups(16 rows) x 2 kslices x 2 bhalves(4 b)

// ---------------- device-global scratch (no allocation allowed) ----------------
__device__ float g_gx[100663296];                       // [1024*64, 1536] input gate pre-acts
__device__ __align__(16) float g_hP[2][NTEAMS][256][16]; // [buf][team][kp][8b x 2par]
__device__ unsigned int g_flag[NCTA];                   // per-CTA publish counters (monotonic)

// ---------------- f32x2 packed-math helpers (Blackwell, PTX-only path) ----------
__device__ __forceinline__ void ffma2(unsigned long long &acc, unsigned long long a,
                                      unsigned long long b) {
    asm("fma.rn.f32x2 %0, %1, %2, %0;" : "+l"(acc) : "l"(a), "l"(b));
}
__device__ __forceinline__ unsigned long long dup2(float a) {
    unsigned long long r; asm("mov.b64 %0, {%1, %1};" : "=l"(r) : "f"(a)); return r;
}
__device__ __forceinline__ unsigned long long pack2(float lo, float hi) {
    unsigned long long r; asm("mov.b64 %0, {%1, %2};" : "=l"(r) : "f"(lo), "f"(hi)); return r;
}
__device__ __forceinline__ float sum2(unsigned long long v) {
    float lo, hi; asm("mov.b64 {%0, %1}, %2;" : "=f"(lo), "=f"(hi) : "l"(v)); return lo + hi;
}
__device__ __forceinline__ float2 unpack2(unsigned long long v) {
    float2 f; asm("mov.b64 {%0, %1}, %2;" : "=f"(f.x), "=f"(f.y) : "l"(v)); return f;
}

// ---------------- flag primitives (gpu scope, L2-coherent) -----------------------
__device__ __forceinline__ unsigned int ld_acq(const unsigned int* p) {
    unsigned int v;
    asm volatile("ld.acquire.gpu.global.u32 %0, [%1];" : "=r"(v) : "l"(p) : "memory");
    return v;
}
__device__ __forceinline__ unsigned int ld_rlx(const unsigned int* p) {
    unsigned int v;
    asm volatile("ld.relaxed.gpu.global.u32 %0, [%1];" : "=r"(v) : "l"(p) : "memory");
    return v;
}
__device__ __forceinline__ void st_rel(unsigned int* p, unsigned int v) {
    asm volatile("st.release.gpu.global.u32 [%0], %1;" :: "l"(p), "r"(v) : "memory");
}
__device__ __forceinline__ void bar_sync(int id, int cnt) {
    asm volatile("bar.sync %0, %1;" :: "r"(id), "r"(cnt) : "memory");
}

// ---------------- dynamic SMEM layout (floats) -- rec kernel ---------------------
#define WP_OFF   0                          // W: [96 rows][512]            (196,608 B)
#define WP_ROW   512
#define RED_OFF  (96 * 512)                 // red: [2 par][2 ks][96][9]    (13,824 B)
#define LENS_OFF (RED_OFF + 2 * 2 * 96 * 9)
#define SMEM_FLOATS (LENS_OFF + 16)
#define SMEM_BYTES  (SMEM_FLOATS * 4)       // 210,496 B (< 232,448 cap)
#define RED_AT(par, ksi, row, b) sm[RED_OFF + (((par) * 2 + (ksi)) * 96 + (row)) * 9 + (b)]

// =================================================================================
// Kernel A: gx[m][n] = sum_k X[m][k] * W[n][k] + bias[n]  (R14 double-buffered)
// =================================================================================
__global__ __launch_bounds__(256) void gemm_gx(const float* __restrict__ X,
                                               const float* __restrict__ W,
                                               const float* __restrict__ bias) {
    __shared__ __align__(16) float As[2][8][128];
    __shared__ __align__(16) float Bs[2][8][128];
    const int tid = threadIdx.x;
    const int m0 = blockIdx.y * 128;
    const int n0 = blockIdx.x * 128;
    const int tx = tid & 15;
    const int ty = tid >> 4;
    const int lrow = tid >> 1;
    const int lk = (tid & 1) * 4;

    unsigned long long acc[8][4];
#pragma unroll
    for (int i = 0; i < 8; i++)
#pragma unroll
        for (int jp = 0; jp < 4; jp++) acc[i][jp] = 0ull;

    const float* xg = X + (size_t)(m0 + lrow) * 512 + lk;
    const float* wg = W + (size_t)(n0 + lrow) * 512 + lk;

    {
        float4 av = *(const float4*)(xg);
        float4 bv = *(const float4*)(wg);
        As[0][lk + 0][lrow] = av.x; As[0][lk + 1][lrow] = av.y;
        As[0][lk + 2][lrow] = av.z; As[0][lk + 3][lrow] = av.w;
        Bs[0][lk + 0][lrow] = bv.x; Bs[0][lk + 1][lrow] = bv.y;
        Bs[0][lk + 2][lrow] = bv.z; Bs[0][lk + 3][lrow] = bv.w;
    }
    __syncthreads();

    for (int k0 = 0; k0 < 512; k0 += 8) {
        const int buf  = (k0 >> 3) & 1;
        const int nbuf = buf ^ 1;
        const bool more = (k0 + 8) < 512;

        float4 av, bv;
        if (more) {
            av = *(const float4*)(xg + k0 + 8);
            bv = *(const float4*)(wg + k0 + 8);
        }

#pragma unroll
        for (int kk = 0; kk < 8; kk++) {
            float4 a0 = *(const float4*)&As[buf][kk][ty * 8];
            float4 a1 = *(const float4*)&As[buf][kk][ty * 8 + 4];
            float4 b0 = *(const float4*)&Bs[buf][kk][tx * 8];
            float4 b1 = *(const float4*)&Bs[buf][kk][tx * 8 + 4];
            unsigned long long bp0 = pack2(b0.x, b0.y);
            unsigned long long bp1 = pack2(b0.z, b0.w);
            unsigned long long bp2 = pack2(b1.x, b1.y);
            unsigned long long bp3 = pack2(b1.z, b1.w);
            float a[8] = {a0.x, a0.y, a0.z, a0.w, a1.x, a1.y, a1.z, a1.w};
#pragma unroll
            for (int i = 0; i < 8; i++) {
                unsigned long long ad = dup2(a[i]);
                ffma2(acc[i][0], ad, bp0);
                ffma2(acc[i][1], ad, bp1);
                ffma2(acc[i][2], ad, bp2);
                ffma2(acc[i][3], ad, bp3);
            }
        }

        if (more) {
            As[nbuf][lk + 0][lrow] = av.x; As[nbuf][lk + 1][lrow] = av.y;
            As[nbuf][lk + 2][lrow] = av.z; As[nbuf][lk + 3][lrow] = av.w;
            Bs[nbuf][lk + 0][lrow] = bv.x; Bs[nbuf][lk + 1][lrow] = bv.y;
            Bs[nbuf][lk + 2][lrow] = bv.z; Bs[nbuf][lk + 3][lrow] = bv.w;
            __syncthreads();
        }
    }

    float bs[8];
#pragma unroll
    for (int c = 0; c < 8; c++) bs[c] = bias[n0 + tx * 8 + c];
#pragma unroll
    for (int i = 0; i < 8; i++) {
        size_t base = (size_t)(m0 + ty * 8 + i) * 1536 + n0 + tx * 8;
        float2 p0 = unpack2(acc[i][0]);
        float2 p1 = unpack2(acc[i][1]);
        float2 p2 = unpack2(acc[i][2]);
        float2 p3 = unpack2(acc[i][3]);
        float4 o0 = make_float4(p0.x + bs[0], p0.y + bs[1], p1.x + bs[2], p1.y + bs[3]);
        float4 o1 = make_float4(p2.x + bs[4], p2.y + bs[5], p3.x + bs[6], p3.y + bs[7]);
        *(float4*)&g_gx[base]     = o0;
        *(float4*)&g_gx[base + 4] = o1;
    }
}

// =================================================================================
// Kernel B: persistent GRU recurrence, 8 teams x 16 CTAs (R15 skeleton), with the
// STAGE PHASE REMOVED: FMA warps read h(t) directly from L2 (__ldcg) with a
// depth-1 software pipeline. L2 has huge headroom (1.3% used); the smem port
// (previous binding pipe) now carries only W reads. One fewer barrier, no staged
// LDG/STS on the critical chain.
//   Team tau owns b = 8i + tau. CTA owns units [32c, 32c+32) -> 96 gate rows.
//   Warp = rowgroup(6 x 16 rows) x kslice(2 x 128 kp) x bhalf(2 x 4 b).
//   Lane = q(8 kp-subs) x s(2 row-halves) x p(2 b-pairs): 8 rows x 32 k x 2 b.
//   Step: warp0 polls 16 team flags -> sync -> FMA (direct-L2 h) -> sync ->
//   gate (256 thr: 32 units x 8 b) -> publish + release.
// =================================================================================
__global__ __launch_bounds__(NTHR, 1) void gru_rec(const float* __restrict__ whh,
                                                   const float* __restrict__ bhh,
                                                   const int* __restrict__ lens,
                                                   float* __restrict__ out) {
    extern __shared__ __align__(16) float sm[];
    int* sm_lens = (int*)&sm[LENS_OFF];

    const int tid  = threadIdx.x;
    const int tau  = blockIdx.x >> 4;        // team 0..7
    const int c    = blockIdx.x & 15;        // CTA within team
    const int wrp  = tid >> 5;
    const int lane = tid & 31;

    // FMA-phase warp mapping
    const int rg = wrp >> 2;                 // rowgroup 0..5 (16 rows each)
    const int ks = (wrp >> 1) & 1;           // kslice 0..1 (128 kp each)
    const int bh = wrp & 1;                  // bhalf 0..1 (4 b each)
    const int q  = lane >> 2;                // kp-sub 0..7
    const int s  = (lane >> 1) & 1;          // row-half 0..1 (8 rows each)
    const int p  = lane & 1;                 // b-pair 0..1
    const int b0 = bh * 4 + 2 * p;           // team-b
    const int rowbase = rg * 16 + s * 8;

    // gate-phase mapping (tid < 256): 32 units x 8 team-b
    const int gu = tid & 31;                 // unit-in-CTA
    const int gb = (tid >> 5) & 7;           // team-b (valid for tid < 256)
    const int bglob = 8 * gb + tau;
    const int j = 32 * c + gu;

    // ---- preload W slice (96 rows x 512) ----
    for (int idx = tid; idx < 96 * 128; idx += NTHR) {
        int row = idx >> 7;
        int k4  = (idx & 127) << 2;
        int g   = row >> 5;
        int u   = row & 31;
        *(float4*)&sm[WP_OFF + row * WP_ROW + k4] =
            *(const float4*)&whh[(size_t)(g * 512 + 32 * c + u) * 512 + k4];
    }
    if (tid < 8) sm_lens[tid] = lens[8 * tid + tau];

    const unsigned int F = ld_rlx(&g_flag[blockIdx.x]); // monotonic across replays

    float bh_r = 0.f, bh_z = 0.f, bh_n = 0.f;
    if (tid < 256) {
        bh_r = bhh[j];
        bh_z = bhh[512 + j];
        bh_n = bhh[1024 + j];
    }
    // h(0) = 0 for this CTA's 16 kp x 16 floats
    if (tid < 256)
        __stcg(&g_hP[0][tau][16 * c + (tid >> 4)][tid & 15], 0.f);
    __syncthreads();
    const int maxlen_team = sm_lens[0];
    const int ml_bh = sm_lens[bh * 4];       // warp b-half max length (descending)
    const int len_b = (tid < 256) ? sm_lens[gb] : 0;
    if (tid == 0) st_rel(&g_flag[blockIdx.x], F + 1);   // h(0) published

    const unsigned int* fp = &g_flag[(tau << 4) + (lane & 15)];
    float hreg = 0.f;

    for (int t = 0; t < 1024; t++) {
        if (t < maxlen_team) {
            // gx prefetch (overlaps poll)
            float gxr = 0.f, gxz = 0.f, gxn = 0.f;
            if (tid < 256) {
                const float* gxp = g_gx + (size_t)(t * 64 + bglob) * 1536 + j;
                gxr = gxp[0];
                gxz = gxp[512];
                gxn = gxp[1024];
            }

            // [poll] warp 0 ONLY waits for all 16 team CTAs to publish h(t)
            if (wrp == 0) {
                const unsigned int tgt = F + 1 + (unsigned)t;
                while (!__all_sync(0xffffffffu, ld_acq(fp) >= tgt)) {}
            }
            __syncthreads();

            // [FMA] 8 rows x 32 k x 2 b per lane, h DIRECT from L2 (depth-1 pipe)
            if (t < ml_bh) {
                // h row pointer: g_hP[buf][tau][kp][16]; element (kp, 2*b0)
                const float* hbase = &g_hP[t & 1][tau][0][2 * b0];

                unsigned long long accA[8], accB[8];
#pragma unroll
                for (int r = 0; r < 8; r++) { accA[r] = 0ull; accB[r] = 0ull; }

                int kp0 = ks * 128 + 2 * q;
                ulonglong2 hA = __ldcg((const ulonglong2*)(hbase + (size_t)kp0 * 16));
                ulonglong2 hB = __ldcg((const ulonglong2*)(hbase + (size_t)(kp0 + 1) * 16));

#pragma unroll
                for (int i = 0; i < 8; i++) {
                    ulonglong2 hA1, hB1;
                    if (i < 7) {
                        int kpn = ks * 128 + (i + 1) * 16 + 2 * q;
                        hA1 = __ldcg((const ulonglong2*)(hbase + (size_t)kpn * 16));
                        hB1 = __ldcg((const ulonglong2*)(hbase + (size_t)(kpn + 1) * 16));
                    }
                    int kp1 = ks * 128 + i * 16 + 2 * q;
#pragma unroll
                    for (int r = 0; r < 8; r++) {
                        ulonglong2 wv = *(const ulonglong2*)
                            &sm[WP_OFF + (rowbase + r) * WP_ROW + 2 * kp1];
                        ffma2(accA[r], hA.x, wv.x);
                        ffma2(accA[r], hB.x, wv.y);
                        ffma2(accB[r], hA.y, wv.x);
                        ffma2(accB[r], hB.y, wv.y);
                    }
                    hA = hA1;
                    hB = hB1;
                }

                // fold q (xor 4,8,16); lanes 0..3 (q==0) store partials
#pragma unroll
                for (int r = 0; r < 8; r++) {
                    float sA = sum2(accA[r]);
                    float sB = sum2(accB[r]);
                    sA += __shfl_xor_sync(0xffffffffu, sA, 4);
                    sB += __shfl_xor_sync(0xffffffffu, sB, 4);
                    sA += __shfl_xor_sync(0xffffffffu, sA, 8);
                    sB += __shfl_xor_sync(0xffffffffu, sB, 8);
                    sA += __shfl_xor_sync(0xffffffffu, sA, 16);
                    sB += __shfl_xor_sync(0xffffffffu, sB, 16);
                    if (lane < 4) {
                        RED_AT(t & 1, ks, rowbase + r, b0)     = sA;
                        RED_AT(t & 1, ks, rowbase + r, b0 + 1) = sB;
                    }
                }
            }
            __syncthreads();                              // red[t&1] complete

            // [gate] 32 units x 8 team-b
            if (tid < 256) {
                float outv = 0.f;
                if (t < len_b) {
                    float ghr = bh_r + RED_AT(t & 1, 0, gu, gb)      + RED_AT(t & 1, 1, gu, gb);
                    float ghz = bh_z + RED_AT(t & 1, 0, 32 + gu, gb) + RED_AT(t & 1, 1, 32 + gu, gb);
                    float ghn = bh_n + RED_AT(t & 1, 0, 64 + gu, gb) + RED_AT(t & 1, 1, 64 + gu, gb);
                    float r = 1.f / (1.f + __expf(-(gxr + ghr)));
                    float z = 1.f / (1.f + __expf(-(gxz + ghz)));
                    float n = tanhf(gxn + r * ghn);
                    hreg = (1.f - z) * n + z * hreg;
                    outv = hreg;
                }
                // publish h(t+1) unit-pair via shfl partner (gu, gu^1 share gb)
                float hpart = __shfl_xor_sync(0xffffffffu, hreg, 1);
                if ((gu & 1) == 0) {
                    float2 v = make_float2(hreg, hpart);
                    __stcg((float2*)&g_hP[(t + 1) & 1][tau][16 * c + (gu >> 1)][2 * gb], v);
                }
                bar_sync(1, 256);                         // all h publishes done
                if (tid == 0) st_rel(&g_flag[blockIdx.x], F + 2 + (unsigned)t);

                out[(size_t)t * 32768 + bglob * 512 + j] = outv;
            }
        } else {
            // whole team finished: zero-fill remaining output rows
            if (tid < 256)
                out[(size_t)t * 32768 + bglob * 512 + j] = 0.f;
        }
    }

    // h_last: [1, B, H]
    if (tid < 256)
        out[(size_t)1024 * 32768 + bglob * 512 + j] = hreg;
}

// =================================================================================
// Inputs (metadata order): x[T,B,I] f32, batch_lengths[B] i32, w_ih[3H,I] f32,
// w_hh[3H,H] f32, b_ih[3H] f32, b_hh[3H] f32.  Output: [T,B,H] then [1,B,H], fp32.
// =================================================================================
extern "C" void kernel_launch(void* const* d_in, const int* in_sizes, int n_in,
                              void* d_out, int out_size) {
    const float* x   = (const float*)d_in[0];
    const int*   len = (const int*)  d_in[1];
    const float* wih = (const float*)d_in[2];
    const float* whh = (const float*)d_in[3];
    const float* bih = (const float*)d_in[4];
    const float* bhh = (const float*)d_in[5];
    float* out = (float*)d_out;

    (void)in_sizes; (void)n_in; (void)out_size;

    cudaFuncSetAttribute(gru_rec, cudaFuncAttributeMaxDynamicSharedMemorySize, SMEM_BYTES);

    gemm_gx<<<dim3(12, 512), 256>>>(x, wih, bih);
    gru_rec<<<NCTA, NTHR, SMEM_BYTES>>>(whh, bhh, len, out);
}